// round 4
// baseline (speedup 1.0000x reference)
#include <cuda_runtime.h>
#include <math.h>

#define T_ 2000
#define B_ 64
#define D_ 512
#define H_ 512
#define TB_ (T_*B_)

// ---- scratch (static device allocations; no cudaMalloc allowed) ----
__device__ float g_wh[TB_*H_];       // 262 MB
__device__ float g_wz[TB_*H_];       // 262 MB
__device__ float g_h1[TB_*H_];       // 262 MB (layer-1 input = layer-0 output)
__device__ float g_hT[H_*B_];        // fallback: hidden state transposed
__device__ float g_zhT[H_*B_];       // fallback: z*h staging transposed
__device__ unsigned int g_bar[8];    // fallback: barrier counters

// =====================================================================
// Stage A: fused dual projection (unchanged; ~8ms both layers)
// =====================================================================
__global__ void __launch_bounds__(256) proj_kernel(
    const float* __restrict__ X,
    const float* __restrict__ Wh, const float* __restrict__ Wz,
    const float* __restrict__ bh, const float* __restrict__ bz,
    float* __restrict__ owh, float* __restrict__ owz)
{
    __shared__ float As[32*64];
    __shared__ float Bhs[32*64];
    __shared__ float Bzs[32*64];

    const int tid = threadIdx.x;
    const int n0 = blockIdx.x * 64;
    const long m0 = (long)blockIdx.y * 64;
    const int pm = tid & 15;
    const int pn = tid >> 4;

    float ah[4][4], az[4][4];
#pragma unroll
    for (int i = 0; i < 4; i++)
#pragma unroll
        for (int j = 0; j < 4; j++) { ah[i][j] = 0.f; az[i][j] = 0.f; }

    for (int k0 = 0; k0 < 512; k0 += 32) {
        __syncthreads();
#pragma unroll
        for (int q = 0; q < 2; q++) {
            int c = tid + 256*q;
            int row = c >> 3;
            int col4 = (c & 7) * 4;
            float4 xa = *(const float4*)&X[(m0 + row)*512 + k0 + col4];
            As[(col4+0)*64+row] = xa.x; As[(col4+1)*64+row] = xa.y;
            As[(col4+2)*64+row] = xa.z; As[(col4+3)*64+row] = xa.w;
            float4 wa = *(const float4*)&Wh[(long)(n0 + row)*512 + k0 + col4];
            Bhs[(col4+0)*64+row] = wa.x; Bhs[(col4+1)*64+row] = wa.y;
            Bhs[(col4+2)*64+row] = wa.z; Bhs[(col4+3)*64+row] = wa.w;
            float4 za = *(const float4*)&Wz[(long)(n0 + row)*512 + k0 + col4];
            Bzs[(col4+0)*64+row] = za.x; Bzs[(col4+1)*64+row] = za.y;
            Bzs[(col4+2)*64+row] = za.z; Bzs[(col4+3)*64+row] = za.w;
        }
        __syncthreads();
#pragma unroll
        for (int kk = 0; kk < 32; kk++) {
            float4 a   = *(float4*)&As [kk*64 + pm*4];
            float4 bh4 = *(float4*)&Bhs[kk*64 + pn*4];
            float4 bz4 = *(float4*)&Bzs[kk*64 + pn*4];
            float av[4] = {a.x, a.y, a.z, a.w};
            float hv[4] = {bh4.x, bh4.y, bh4.z, bh4.w};
            float zv[4] = {bz4.x, bz4.y, bz4.z, bz4.w};
#pragma unroll
            for (int i = 0; i < 4; i++)
#pragma unroll
                for (int j = 0; j < 4; j++) {
                    ah[i][j] += av[i]*hv[j];
                    az[i][j] += av[i]*zv[j];
                }
        }
    }

    float bb_h[4], bb_z[4];
#pragma unroll
    for (int j = 0; j < 4; j++) { bb_h[j] = bh[n0 + pn*4 + j]; bb_z[j] = bz[n0 + pn*4 + j]; }
#pragma unroll
    for (int i = 0; i < 4; i++) {
        long r = (m0 + pm*4 + i)*512 + n0 + pn*4;
        float4 oh, oz;
        oh.x = ah[i][0]+bb_h[0]; oh.y = ah[i][1]+bb_h[1];
        oh.z = ah[i][2]+bb_h[2]; oh.w = ah[i][3]+bb_h[3];
        oz.x = az[i][0]+bb_z[0]; oz.y = az[i][1]+bb_z[1];
        oz.z = az[i][2]+bb_z[2]; oz.w = az[i][3]+bb_z[3];
        *(float4*)&owh[r] = oh;
        *(float4*)&owz[r] = oz;
    }
}

// =====================================================================
// PTX helpers for the cluster scan
// =====================================================================
__device__ __forceinline__ unsigned smem_u32(const void* p) {
    return (unsigned)__cvta_generic_to_shared(p);
}
__device__ __forceinline__ void mbar_init(unsigned mb, unsigned cnt) {
    asm volatile("mbarrier.init.shared.b64 [%0], %1;" :: "r"(mb), "r"(cnt) : "memory");
}
__device__ __forceinline__ void mbar_expect_tx(unsigned mb, unsigned bytes) {
    asm volatile("mbarrier.arrive.expect_tx.shared.b64 _, [%0], %1;"
                 :: "r"(mb), "r"(bytes) : "memory");
}
__device__ __forceinline__ void mbar_wait(unsigned mb, unsigned phase) {
    unsigned done;
    asm volatile("{\n\t.reg .pred p;\n\t"
        "mbarrier.try_wait.parity.acquire.cta.shared::cta.b64 p, [%1], %2, 0x989680;\n\t"
        "selp.b32 %0, 1, 0, p;\n\t}"
        : "=r"(done) : "r"(mb), "r"(phase) : "memory");
    while (!done) {
        asm volatile("{\n\t.reg .pred p;\n\t"
            "mbarrier.try_wait.parity.acquire.cta.shared::cta.b64 p, [%1], %2, 0x989680;\n\t"
            "selp.b32 %0, 1, 0, p;\n\t}"
            : "=r"(done) : "r"(mb), "r"(phase) : "memory");
    }
}
// push one float to the same smem slot in all 16 cluster CTAs,
// each store signals the target CTA's mbarrier with 4 tx bytes.
__device__ __forceinline__ void push16(float v, unsigned slot, unsigned mbar) {
    unsigned u = __float_as_uint(v);
#pragma unroll
    for (int c = 0; c < 16; c++) {
        unsigned d, m;
        asm volatile("mapa.shared::cluster.u32 %0, %1, %2;" : "=r"(d) : "r"(slot), "r"(c));
        asm volatile("mapa.shared::cluster.u32 %0, %1, %2;" : "=r"(m) : "r"(mbar), "r"(c));
        asm volatile("st.async.shared::cluster.mbarrier::complete_tx::bytes.b32 [%0], %1, [%2];"
                     :: "r"(d), "r"(u), "r"(m) : "memory");
    }
}

// =====================================================================
// Stage B (primary): cluster-16 persistent GRU scan.
// Grid: 128 CTAs = 8 clusters(batch groups of 8) x 16 H-slices (32 each).
// Exchange is pure DSMEM push (st.async) + mbarrier tx accounting.
// FIX vs round 3: terminal mbH wait + cluster barrier before exit so no
// CTA tears down its SMEM while peers' st.async are in flight.
// =====================================================================
#define CL_SMEM_FLOATS (4 + 16384*2 + 4096*2 + 4096)
#define CL_SMEM_BYTES  (CL_SMEM_FLOATS*4)
#define PHASE_TX 16384u   // 16 CTAs x 256 threads x 4B

__global__ void __launch_bounds__(256) scan_cluster_kernel(
    const float* __restrict__ wh, const float* __restrict__ wz,
    const float* __restrict__ Uh, const float* __restrict__ Uz,
    float* __restrict__ out)
{
    extern __shared__ float sm[];
    float* Uzs  = sm + 4;             // 512*32
    float* Uhs  = Uzs + 16384;        // 512*32
    float* hx_h = Uhs + 16384;        // [j][8b]  h(t-1)
    float* hx_z = hx_h + 4096;        // [j][8b]  z*h
    float* red  = hx_z + 4096;        // 16*256 partials

    const unsigned mbZ = smem_u32(sm);       // 8B
    const unsigned mbH = mbZ + 8;            // 8B

    const int tid = threadIdx.x;
    const int gh  = blockIdx.x & 15;   // H slice (== cluster rank)
    const int gb  = blockIdx.x >> 4;   // batch group
    const int b0  = gb * 8;
    const int i0  = gh * 32;

    if (tid == 0) { mbar_init(mbZ, 1); mbar_init(mbH, 1); }

    // one-time U slice load (j-major)
    for (int idx = tid; idx < 32*512; idx += 256) {
        int i = idx >> 9;
        int j = idx & 511;
        Uzs[j*32 + i] = Uz[(i0 + i)*512 + j];
        Uhs[j*32 + i] = Uh[(i0 + i)*512 + j];
    }
    // h(0) = 0
    for (int i = tid; i < 4096; i += 256) hx_h[i] = 0.f;
    __syncthreads();

    // all CTAs' mbarriers + buffers ready before any peer pushes
    asm volatile("barrier.cluster.arrive.aligned;" ::: "memory");
    asm volatile("barrier.cluster.wait.aligned;"   ::: "memory");

    // GEMM layout: ks = K-split (32 j each), pos covers (2 batch-quads x 8 i-quads)
    const int ks = tid >> 4;
    const int pos = tid & 15;
    const int pb = pos >> 3;
    const int pi = pos & 7;
    const int jbase = ks * 32;

    // output ownership: 1 (b,i) per thread
    const int bl = tid >> 5;           // local batch 0..7
    const int il = tid & 31;           // local i 0..31
    const int jg = i0 + il;
    const unsigned slot_z = smem_u32(hx_z) + (unsigned)(jg*8 + bl)*4u;
    const unsigned slot_h = smem_u32(hx_h) + (unsigned)(jg*8 + bl)*4u;

    float h_own = 0.f;

    for (int t = 0; t < T_; t++) {
        long base = ((long)(t*B_) + b0 + bl)*(long)H_ + jg;
        float wzv = __ldcg(wz + base);
        float whv = __ldcg(wh + base);

        // wait for h(t-1) pushes (skip at t=0: hx_h pre-zeroed)
        if (t > 0) mbar_wait(mbH, (unsigned)((t-1) & 1));
        if (tid == 0) mbar_expect_tx(mbZ, PHASE_TX);

        // ---- GEMM z from hx_h ----
        float a00,a01,a02,a03,a10,a11,a12,a13,a20,a21,a22,a23,a30,a31,a32,a33;
        a00=a01=a02=a03=a10=a11=a12=a13=a20=a21=a22=a23=a30=a31=a32=a33=0.f;
        {
            const float* hp = hx_h + jbase*8 + pb*4;
            const float* up = Uzs + jbase*32 + pi*4;
#pragma unroll
            for (int kk = 0; kk < 32; kk++) {
                float4 hv = *(const float4*)hp; hp += 8;
                float4 uv = *(const float4*)up; up += 32;
                a00 += hv.x*uv.x; a01 += hv.x*uv.y; a02 += hv.x*uv.z; a03 += hv.x*uv.w;
                a10 += hv.y*uv.x; a11 += hv.y*uv.y; a12 += hv.y*uv.z; a13 += hv.y*uv.w;
                a20 += hv.z*uv.x; a21 += hv.z*uv.y; a22 += hv.z*uv.z; a23 += hv.z*uv.w;
                a30 += hv.w*uv.x; a31 += hv.w*uv.y; a32 += hv.w*uv.z; a33 += hv.w*uv.w;
            }
        }
        {
            float* rp = red + ks*256 + pb*128 + pi*4;
            *(float4*)(rp     ) = make_float4(a00,a01,a02,a03);
            *(float4*)(rp + 32) = make_float4(a10,a11,a12,a13);
            *(float4*)(rp + 64) = make_float4(a20,a21,a22,a23);
            *(float4*)(rp + 96) = make_float4(a30,a31,a32,a33);
        }
        __syncthreads();   // also: all hx_h reads done before any zh push

        float s = 0.f;
#pragma unroll
        for (int k2 = 0; k2 < 16; k2++) s += red[k2*256 + tid];

        float z  = __fdividef(1.f, 1.f + __expf(-(s + wzv)));
        float zh = z * h_own;

        push16(zh, slot_z, mbZ);
        mbar_wait(mbZ, (unsigned)(t & 1));
        if (tid == 0) mbar_expect_tx(mbH, PHASE_TX);

        // ---- GEMM h from hx_z ----
        a00=a01=a02=a03=a10=a11=a12=a13=a20=a21=a22=a23=a30=a31=a32=a33=0.f;
        {
            const float* hp = hx_z + jbase*8 + pb*4;
            const float* up = Uhs + jbase*32 + pi*4;
#pragma unroll
            for (int kk = 0; kk < 32; kk++) {
                float4 hv = *(const float4*)hp; hp += 8;
                float4 uv = *(const float4*)up; up += 32;
                a00 += hv.x*uv.x; a01 += hv.x*uv.y; a02 += hv.x*uv.z; a03 += hv.x*uv.w;
                a10 += hv.y*uv.x; a11 += hv.y*uv.y; a12 += hv.y*uv.z; a13 += hv.y*uv.w;
                a20 += hv.z*uv.x; a21 += hv.z*uv.y; a22 += hv.z*uv.z; a23 += hv.z*uv.w;
                a30 += hv.w*uv.x; a31 += hv.w*uv.y; a32 += hv.w*uv.z; a33 += hv.w*uv.w;
            }
        }
        {
            float* rp = red + ks*256 + pb*128 + pi*4;
            *(float4*)(rp     ) = make_float4(a00,a01,a02,a03);
            *(float4*)(rp + 32) = make_float4(a10,a11,a12,a13);
            *(float4*)(rp + 64) = make_float4(a20,a21,a22,a23);
            *(float4*)(rp + 96) = make_float4(a30,a31,a32,a33);
        }
        __syncthreads();   // all hx_z reads done before any h push

        float s2 = 0.f;
#pragma unroll
        for (int k2 = 0; k2 < 16; k2++) s2 += red[k2*256 + tid];

        float ahv = s2 + whv;
        float hc = __fdividef(2.f, 1.f + __expf(-2.f*ahv)) - 1.f;
        float hn = zh + (1.f - z)*hc;
        h_own = hn;

        push16(hn, slot_h, mbH);
        out[base] = hn;
    }

    // -------- termination safety (the round-3 bug fix) --------
    // 1) absorb the final hn pushes so our mbarrier accounting is complete
    mbar_wait(mbH, (unsigned)((T_-1) & 1));
    // 2) no CTA may exit while a peer's st.async toward our SMEM could be
    //    in flight: full cluster barrier before teardown.
    __syncthreads();
    asm volatile("barrier.cluster.arrive.aligned;" ::: "memory");
    asm volatile("barrier.cluster.wait.aligned;"   ::: "memory");
}

// =====================================================================
// Stage B (fallback): round-2 global-barrier scan (known good)
// =====================================================================
#define SCAN_SMEM_BYTES ((64+64+16+16)*1024)

__global__ void __launch_bounds__(256) scan_kernel(
    const float* __restrict__ wh, const float* __restrict__ wz,
    const float* __restrict__ Uh, const float* __restrict__ Uz,
    float* __restrict__ out,
    float* __restrict__ hT, float* __restrict__ zhT,
    unsigned int* __restrict__ bar)
{
    extern __shared__ float sm[];
    float* Uzs = sm;
    float* Uhs = sm + 16384;
    float* hx  = sm + 32768;
    float* red = sm + 32768 + 4096;

    const int tid  = threadIdx.x;
    const int gb   = blockIdx.x >> 4;
    const int gh   = blockIdx.x & 15;
    const int b0   = gb * 8;
    const int i0   = gh * 32;
    const int warp = tid >> 5;
    const int lane = tid & 31;

    for (int idx = tid; idx < 32*512; idx += 256) {
        int i = idx >> 9;
        int j = idx & 511;
        Uzs[j*32 + i] = Uz[(i0 + i)*512 + j];
        Uhs[j*32 + i] = Uh[(i0 + i)*512 + j];
    }
    __syncthreads();

    const int ks = tid >> 4;
    const int pos = tid & 15;
    const int pb = pos >> 3;
    const int pi = pos & 7;
    const int jbase = ks * 32;

    const int bl = tid >> 5;
    const int il = tid & 31;
    const int jg = i0 + il;
    const int xpos = jg*64 + b0 + bl;

    unsigned int* barp = bar + gb;
    float h_own = 0.f;

    for (int t = 0; t < T_; t++) {
        long base = ((long)(t*B_) + b0 + bl)*(long)H_ + jg;
        float wzv = __ldcg(wz + base);
        float whv = __ldcg(wh + base);

        if (tid == 0) {
            unsigned tgt = (unsigned)(2*t) * 16u;
            while (*(volatile unsigned*)barp < tgt) {}
            __threadfence();
        }
        __syncthreads();

#pragma unroll
        for (int it = 0; it < 4; it++) {
            int fq = it*32 + lane;
            int j  = (warp << 6) + (fq >> 1);
            int hf = fq & 1;
            float4 v = __ldcg((const float4*)(hT + j*64 + b0 + hf*4));
            *(float4*)(hx + j*8 + hf*4) = v;
        }
        __syncwarp();

        float a00,a01,a02,a03,a10,a11,a12,a13,a20,a21,a22,a23,a30,a31,a32,a33;
        a00=a01=a02=a03=a10=a11=a12=a13=a20=a21=a22=a23=a30=a31=a32=a33=0.f;
        {
            const float* hp = hx + jbase*8 + pb*4;
            const float* up = Uzs + jbase*32 + pi*4;
#pragma unroll
            for (int kk = 0; kk < 32; kk++) {
                float4 hv = *(const float4*)hp; hp += 8;
                float4 uv = *(const float4*)up; up += 32;
                a00 += hv.x*uv.x; a01 += hv.x*uv.y; a02 += hv.x*uv.z; a03 += hv.x*uv.w;
                a10 += hv.y*uv.x; a11 += hv.y*uv.y; a12 += hv.y*uv.z; a13 += hv.y*uv.w;
                a20 += hv.z*uv.x; a21 += hv.z*uv.y; a22 += hv.z*uv.z; a23 += hv.z*uv.w;
                a30 += hv.w*uv.x; a31 += hv.w*uv.y; a32 += hv.w*uv.z; a33 += hv.w*uv.w;
            }
        }
        {
            float* rp = red + ks*256 + pb*128 + pi*4;
            *(float4*)(rp     ) = make_float4(a00,a01,a02,a03);
            *(float4*)(rp + 32) = make_float4(a10,a11,a12,a13);
            *(float4*)(rp + 64) = make_float4(a20,a21,a22,a23);
            *(float4*)(rp + 96) = make_float4(a30,a31,a32,a33);
        }
        __syncthreads();

        float s = 0.f;
#pragma unroll
        for (int k2 = 0; k2 < 16; k2++) s += red[k2*256 + tid];

        float z  = __fdividef(1.f, 1.f + __expf(-(s + wzv)));
        float zh = z * h_own;
        zhT[xpos] = zh;
        __syncthreads();
        if (tid == 0) { __threadfence(); atomicAdd(barp, 1u); }

        if (tid == 0) {
            unsigned tgt = (unsigned)(2*t + 1) * 16u;
            while (*(volatile unsigned*)barp < tgt) {}
            __threadfence();
        }
        __syncthreads();

#pragma unroll
        for (int it = 0; it < 4; it++) {
            int fq = it*32 + lane;
            int j  = (warp << 6) + (fq >> 1);
            int hf = fq & 1;
            float4 v = __ldcg((const float4*)(zhT + j*64 + b0 + hf*4));
            *(float4*)(hx + j*8 + hf*4) = v;
        }
        __syncwarp();

        a00=a01=a02=a03=a10=a11=a12=a13=a20=a21=a22=a23=a30=a31=a32=a33=0.f;
        {
            const float* hp = hx + jbase*8 + pb*4;
            const float* up = Uhs + jbase*32 + pi*4;
#pragma unroll
            for (int kk = 0; kk < 32; kk++) {
                float4 hv = *(const float4*)hp; hp += 8;
                float4 uv = *(const float4*)up; up += 32;
                a00 += hv.x*uv.x; a01 += hv.x*uv.y; a02 += hv.x*uv.z; a03 += hv.x*uv.w;
                a10 += hv.y*uv.x; a11 += hv.y*uv.y; a12 += hv.y*uv.z; a13 += hv.y*uv.w;
                a20 += hv.z*uv.x; a21 += hv.z*uv.y; a22 += hv.z*uv.z; a23 += hv.z*uv.w;
                a30 += hv.w*uv.x; a31 += hv.w*uv.y; a32 += hv.w*uv.z; a33 += hv.w*uv.w;
            }
        }
        {
            float* rp = red + ks*256 + pb*128 + pi*4;
            *(float4*)(rp     ) = make_float4(a00,a01,a02,a03);
            *(float4*)(rp + 32) = make_float4(a10,a11,a12,a13);
            *(float4*)(rp + 64) = make_float4(a20,a21,a22,a23);
            *(float4*)(rp + 96) = make_float4(a30,a31,a32,a33);
        }
        __syncthreads();

        float s2 = 0.f;
#pragma unroll
        for (int k2 = 0; k2 < 16; k2++) s2 += red[k2*256 + tid];

        float ahv = s2 + whv;
        float hc = __fdividef(2.f, 1.f + __expf(-2.f*ahv)) - 1.f;
        float hn = zh + (1.f - z)*hc;
        h_own = hn;
        hT[xpos] = hn;
        out[base] = hn;
        __syncthreads();
        if (tid == 0) { __threadfence(); atomicAdd(barp, 1u); }
    }
}

// =====================================================================
extern "C" void kernel_launch(void* const* d_in, const int* in_sizes, int n_in,
                              void* d_out, int out_size)
{
    const float* x   = (const float*)d_in[0];
    const float* Wh0 = (const float*)d_in[1];
    const float* bh0 = (const float*)d_in[2];
    const float* Wz0 = (const float*)d_in[3];
    const float* bz0 = (const float*)d_in[4];
    const float* Uh0 = (const float*)d_in[5];
    const float* Uz0 = (const float*)d_in[6];
    const float* Wh1 = (const float*)d_in[7];
    const float* bh1 = (const float*)d_in[8];
    const float* Wz1 = (const float*)d_in[9];
    const float* bz1 = (const float*)d_in[10];
    const float* Uh1 = (const float*)d_in[11];
    const float* Uz1 = (const float*)d_in[12];
    float* out = (float*)d_out;

    float *p_wh, *p_wz, *p_h1, *p_hT, *p_zhT;
    unsigned int* p_bar;
    cudaGetSymbolAddress((void**)&p_wh, g_wh);
    cudaGetSymbolAddress((void**)&p_wz, g_wz);
    cudaGetSymbolAddress((void**)&p_h1, g_h1);
    cudaGetSymbolAddress((void**)&p_hT, g_hT);
    cudaGetSymbolAddress((void**)&p_zhT, g_zhT);
    cudaGetSymbolAddress((void**)&p_bar, g_bar);

    cudaError_t e1 = cudaFuncSetAttribute(scan_cluster_kernel,
                         cudaFuncAttributeMaxDynamicSharedMemorySize, CL_SMEM_BYTES);
    cudaError_t e2 = cudaFuncSetAttribute(scan_cluster_kernel,
                         cudaFuncAttributeNonPortableClusterSizeAllowed, 1);
    cudaFuncSetAttribute(scan_kernel,
                         cudaFuncAttributeMaxDynamicSharedMemorySize, SCAN_SMEM_BYTES);

    // cluster-16 capability probe (host-side query; capture-safe)
    cudaLaunchConfig_t cfg = {};
    cfg.gridDim = dim3(128, 1, 1);
    cfg.blockDim = dim3(256, 1, 1);
    cfg.dynamicSmemBytes = CL_SMEM_BYTES;
    cfg.stream = 0;
    cudaLaunchAttribute at[1];
    at[0].id = cudaLaunchAttributeClusterDimension;
    at[0].val.clusterDim.x = 16;
    at[0].val.clusterDim.y = 1;
    at[0].val.clusterDim.z = 1;
    cfg.attrs = at;
    cfg.numAttrs = 1;

    int ncl = 0;
    cudaError_t qe = cudaOccupancyMaxActiveClusters(&ncl, scan_cluster_kernel, &cfg);
    bool use_cluster = (e1 == cudaSuccess && e2 == cudaSuccess &&
                        qe == cudaSuccess && ncl >= 8);
    cudaGetLastError();  // clear any sticky error from the probe

    dim3 pgrid(8, 2000);

    // ---- Layer 0 ----
    proj_kernel<<<pgrid, 256>>>(x, Wh0, Wz0, bh0, bz0, p_wh, p_wz);
    if (use_cluster) {
        cudaError_t le = cudaLaunchKernelEx(&cfg, scan_cluster_kernel,
                           (const float*)p_wh, (const float*)p_wz, Uh0, Uz0, p_h1);
        if (le != cudaSuccess) {
            use_cluster = false;
            cudaGetLastError();
            cudaMemsetAsync(p_hT, 0, H_*B_*sizeof(float));
            cudaMemsetAsync(p_bar, 0, 8*sizeof(unsigned int));
            scan_kernel<<<128, 256, SCAN_SMEM_BYTES>>>(p_wh, p_wz, Uh0, Uz0,
                                                       p_h1, p_hT, p_zhT, p_bar);
        }
    } else {
        cudaMemsetAsync(p_hT, 0, H_*B_*sizeof(float));
        cudaMemsetAsync(p_bar, 0, 8*sizeof(unsigned int));
        scan_kernel<<<128, 256, SCAN_SMEM_BYTES>>>(p_wh, p_wz, Uh0, Uz0,
                                                   p_h1, p_hT, p_zhT, p_bar);
    }

    // ---- Layer 1 ----
    proj_kernel<<<pgrid, 256>>>(p_h1, Wh1, Wz1, bh1, bz1, p_wh, p_wz);
    if (use_cluster) {
        cudaLaunchKernelEx(&cfg, scan_cluster_kernel,
                           (const float*)p_wh, (const float*)p_wz, Uh1, Uz1, out);
    } else {
        cudaMemsetAsync(p_hT, 0, H_*B_*sizeof(float));
        cudaMemsetAsync(p_bar, 0, 8*sizeof(unsigned int));
        scan_kernel<<<128, 256, SCAN_SMEM_BYTES>>>(p_wh, p_wz, Uh1, Uz1,
                                                   out, p_hT, p_zhT, p_bar);
    }
}

// round 5
// speedup vs baseline: 1.0551x; 1.0551x over previous
#include <cuda_runtime.h>
#include <math.h>

#define T_ 2000
#define B_ 64
#define D_ 512
#define H_ 512
#define TB_ (T_*B_)

// ---- scratch (static device allocations; no cudaMalloc allowed) ----
__device__ float g_wh[TB_*H_];        // 262 MB
__device__ float g_wz[TB_*H_];        // 262 MB
__device__ float g_h1[TB_*H_];        // 262 MB (layer-1 input = layer-0 output)
__device__ float g_hT2[16*512*4];     // hidden state, [group][j][4b]
__device__ float g_zhT2[16*512*4];    // z*h staging, [group][j][4b]
__device__ unsigned int g_bar[16];    // barrier counter per batch-group

// =====================================================================
// Stage A: fused dual projection  owh = X@Wh^T + bh, owz = X@Wz^T + bz
// (unchanged; ~8ms for both layers — at fp32 FFMA roofline)
// =====================================================================
__global__ void __launch_bounds__(256) proj_kernel(
    const float* __restrict__ X,
    const float* __restrict__ Wh, const float* __restrict__ Wz,
    const float* __restrict__ bh, const float* __restrict__ bz,
    float* __restrict__ owh, float* __restrict__ owz)
{
    __shared__ float As[32*64];
    __shared__ float Bhs[32*64];
    __shared__ float Bzs[32*64];

    const int tid = threadIdx.x;
    const int n0 = blockIdx.x * 64;
    const long m0 = (long)blockIdx.y * 64;
    const int pm = tid & 15;
    const int pn = tid >> 4;

    float ah[4][4], az[4][4];
#pragma unroll
    for (int i = 0; i < 4; i++)
#pragma unroll
        for (int j = 0; j < 4; j++) { ah[i][j] = 0.f; az[i][j] = 0.f; }

    for (int k0 = 0; k0 < 512; k0 += 32) {
        __syncthreads();
#pragma unroll
        for (int q = 0; q < 2; q++) {
            int c = tid + 256*q;
            int row = c >> 3;
            int col4 = (c & 7) * 4;
            float4 xa = *(const float4*)&X[(m0 + row)*512 + k0 + col4];
            As[(col4+0)*64+row] = xa.x; As[(col4+1)*64+row] = xa.y;
            As[(col4+2)*64+row] = xa.z; As[(col4+3)*64+row] = xa.w;
            float4 wa = *(const float4*)&Wh[(long)(n0 + row)*512 + k0 + col4];
            Bhs[(col4+0)*64+row] = wa.x; Bhs[(col4+1)*64+row] = wa.y;
            Bhs[(col4+2)*64+row] = wa.z; Bhs[(col4+3)*64+row] = wa.w;
            float4 za = *(const float4*)&Wz[(long)(n0 + row)*512 + k0 + col4];
            Bzs[(col4+0)*64+row] = za.x; Bzs[(col4+1)*64+row] = za.y;
            Bzs[(col4+2)*64+row] = za.z; Bzs[(col4+3)*64+row] = za.w;
        }
        __syncthreads();
#pragma unroll
        for (int kk = 0; kk < 32; kk++) {
            float4 a   = *(float4*)&As [kk*64 + pm*4];
            float4 bh4 = *(float4*)&Bhs[kk*64 + pn*4];
            float4 bz4 = *(float4*)&Bzs[kk*64 + pn*4];
            float av[4] = {a.x, a.y, a.z, a.w};
            float hv[4] = {bh4.x, bh4.y, bh4.z, bh4.w};
            float zv[4] = {bz4.x, bz4.y, bz4.z, bz4.w};
#pragma unroll
            for (int i = 0; i < 4; i++)
#pragma unroll
                for (int j = 0; j < 4; j++) {
                    ah[i][j] += av[i]*hv[j];
                    az[i][j] += av[i]*zv[j];
                }
        }
    }

    float bb_h[4], bb_z[4];
#pragma unroll
    for (int j = 0; j < 4; j++) { bb_h[j] = bh[n0 + pn*4 + j]; bb_z[j] = bz[n0 + pn*4 + j]; }
#pragma unroll
    for (int i = 0; i < 4; i++) {
        long r = (m0 + pm*4 + i)*512 + n0 + pn*4;
        float4 oh, oz;
        oh.x = ah[i][0]+bb_h[0]; oh.y = ah[i][1]+bb_h[1];
        oh.z = ah[i][2]+bb_h[2]; oh.w = ah[i][3]+bb_h[3];
        oz.x = az[i][0]+bb_z[0]; oz.y = az[i][1]+bb_z[1];
        oz.z = az[i][2]+bb_z[2]; oz.w = az[i][3]+bb_z[3];
        *(float4*)&owh[r] = oh;
        *(float4*)&owz[r] = oz;
    }
}

// =====================================================================
// Stage B: persistent dual-group GRU scan (latency hiding by interleave).
// Grid: 128 CTAs = 8 pairs x 16 H-slices. CTA (p, s) serves batch groups
// gA=p and gB=p+8 (4 batches each) for H slice [s*32, s*32+32).
// Per step: Z_A, Z_B, H_A, H_B — every cross-CTA dependency is masked by
// one phase of the other group's compute, so barrier waits are ~instant.
// =====================================================================
#define SCAN2_SMEM_FLOATS (16384*2 + 2048*2 + 2048)
#define SCAN2_SMEM_BYTES  (SCAN2_SMEM_FLOATS*4)

__device__ __forceinline__ void wait_flag(const unsigned int* f, unsigned tgt)
{
    unsigned v;
    do {
        asm volatile("ld.global.acquire.gpu.u32 %0, [%1];" : "=r"(v) : "l"(f));
    } while (v < tgt);
}

__device__ __forceinline__ void stage_group(float* __restrict__ hx,
                                            const float* __restrict__ src,
                                            int warp, int lane)
{
    // warp w stages j in [w*64, w*64+64): 256 floats = 64 float4
    const float4* s4 = (const float4*)(src + (warp << 8));
    float4* d4 = (float4*)(hx + (warp << 8));
    d4[lane]      = __ldcg(s4 + lane);
    d4[lane + 32] = __ldcg(s4 + lane + 32);
    __syncwarp();
}

// GEMM over one group's hx [512 j][4 b] against Us [512 j][32 i] slice.
// Thread layout: ks = tid>>4 (16 K-splits of 32 j), pos = tid&15:
// pb = pos>>3 (2 batches each), pi = pos&7 (4 i each).
// Returns the reduced dot for output (bl=tid&3, il=tid>>2) when tid<128.
__device__ __forceinline__ float gemm_phase(const float* __restrict__ hx,
                                            const float* __restrict__ Us,
                                            float* __restrict__ red, int tid)
{
    const int ks = tid >> 4;
    const int pos = tid & 15;
    const int pb = pos >> 3;
    const int pi = pos & 7;
    const int jbase = ks * 32;

    float a0x=0.f,a0y=0.f,a0z=0.f,a0w=0.f;
    float a1x=0.f,a1y=0.f,a1z=0.f,a1w=0.f;
    const float* hp = hx + jbase*4 + pb*2;
    const float* up = Us + jbase*32 + pi*4;
#pragma unroll
    for (int kk = 0; kk < 32; kk++) {
        float2 hv = *(const float2*)hp; hp += 4;
        float4 uv = *(const float4*)up; up += 32;
        a0x += hv.x*uv.x; a0y += hv.x*uv.y; a0z += hv.x*uv.z; a0w += hv.x*uv.w;
        a1x += hv.y*uv.x; a1y += hv.y*uv.y; a1z += hv.y*uv.z; a1w += hv.y*uv.w;
    }
    {
        float* rp = red + ks*128 + (pb*2)*32 + pi*4;
        *(float4*)(rp)      = make_float4(a0x,a0y,a0z,a0w);
        *(float4*)(rp + 32) = make_float4(a1x,a1y,a1z,a1w);
    }
    __syncthreads();

    float s = 0.f;
    if (tid < 128) {
        const int bl = tid & 3;
        const int il = tid >> 2;
#pragma unroll
        for (int k2 = 0; k2 < 16; k2++) s += red[k2*128 + bl*32 + il];
    }
    return s;
}

__global__ void __launch_bounds__(256) scan2_kernel(
    const float* __restrict__ wh, const float* __restrict__ wz,
    const float* __restrict__ Uh, const float* __restrict__ Uz,
    float* __restrict__ out,
    float* __restrict__ hT2, float* __restrict__ zhT2,
    unsigned int* __restrict__ bar)
{
    extern __shared__ float sm[];
    float* Uzs = sm;                   // 512*32
    float* Uhs = sm + 16384;           // 512*32
    float* hxA = sm + 32768;           // 512*4
    float* hxB = hxA + 2048;           // 512*4
    float* red = hxB + 2048;           // 16*128

    const int tid  = threadIdx.x;
    const int s    = blockIdx.x & 15;   // H slice
    const int p    = blockIdx.x >> 4;   // pair 0..7
    const int i0   = s * 32;
    const int gA   = p;
    const int gB   = p + 8;
    const int warp = tid >> 5;
    const int lane = tid & 31;

    // one-time U slice load (j-major)
    for (int idx = tid; idx < 32*512; idx += 256) {
        int i = idx >> 9;
        int j = idx & 511;
        Uzs[j*32 + i] = Uz[(i0 + i)*512 + j];
        Uhs[j*32 + i] = Uh[(i0 + i)*512 + j];
    }
    __syncthreads();

    // output ownership (tid < 128): bl = tid&3 (local batch), il = tid>>2
    const int bl = tid & 3;
    const int il = tid >> 2;
    const int jg = i0 + il;
    const bool owner = tid < 128;
    const int xoff = jg*4 + bl;        // offset within a group's [j][4] block

    float* hTA  = hT2  + gA*2048;  float* hTB  = hT2  + gB*2048;
    float* zhTA = zhT2 + gA*2048;  float* zhTB = zhT2 + gB*2048;
    unsigned int* barA = bar + gA;
    unsigned int* barB = bar + gB;

    float hA = 0.f, hB = 0.f;          // owned h(t-1) values

    for (int t = 0; t < T_; t++) {
        long baseA = ((long)(t*B_) + gA*4 + bl)*(long)H_ + jg;
        long baseB = ((long)(t*B_) + gB*4 + bl)*(long)H_ + jg;
        float wzA = 0.f, whA = 0.f, wzB = 0.f, whB = 0.f;
        if (owner) {
            wzA = __ldcg(wz + baseA); whA = __ldcg(wh + baseA);
            wzB = __ldcg(wz + baseB); whB = __ldcg(wh + baseB);
        }

        unsigned tgtZ = (unsigned)(2*t) * 16u;
        unsigned tgtH = (unsigned)(2*t + 1) * 16u;

        // ================= Z_A =================
        wait_flag(barA, tgtZ);
        stage_group(hxA, hTA, warp, lane);
        float sA = gemm_phase(hxA, Uzs, red, tid);
        float zA = 0.f, zhA = 0.f;
        if (owner) {
            zA  = __fdividef(1.f, 1.f + __expf(-(sA + wzA)));
            zhA = zA * hA;
            zhTA[xoff] = zhA;
        }
        __syncthreads();
        if (tid == 0) { __threadfence(); atomicAdd(barA, 1u); }

        // ================= Z_B =================
        wait_flag(barB, tgtZ);
        stage_group(hxB, hTB, warp, lane);
        float sB = gemm_phase(hxB, Uzs, red, tid);
        float zB = 0.f, zhB = 0.f;
        if (owner) {
            zB  = __fdividef(1.f, 1.f + __expf(-(sB + wzB)));
            zhB = zB * hB;
            zhTB[xoff] = zhB;
        }
        __syncthreads();
        if (tid == 0) { __threadfence(); atomicAdd(barB, 1u); }

        // ================= H_A =================
        wait_flag(barA, tgtH);
        stage_group(hxA, zhTA, warp, lane);
        float s2A = gemm_phase(hxA, Uhs, red, tid);
        if (owner) {
            float ahv = s2A + whA;
            float hc = __fdividef(2.f, 1.f + __expf(-2.f*ahv)) - 1.f;
            hA = zhA + (1.f - zA)*hc;
            hTA[xoff] = hA;
            out[baseA] = hA;
        }
        __syncthreads();
        if (tid == 0) { __threadfence(); atomicAdd(barA, 1u); }

        // ================= H_B =================
        wait_flag(barB, tgtH);
        stage_group(hxB, zhTB, warp, lane);
        float s2B = gemm_phase(hxB, Uhs, red, tid);
        if (owner) {
            float ahv = s2B + whB;
            float hc = __fdividef(2.f, 1.f + __expf(-2.f*ahv)) - 1.f;
            hB = zhB + (1.f - zB)*hc;
            hTB[xoff] = hB;
            out[baseB] = hB;
        }
        __syncthreads();
        if (tid == 0) { __threadfence(); atomicAdd(barB, 1u); }
    }
}

// =====================================================================
extern "C" void kernel_launch(void* const* d_in, const int* in_sizes, int n_in,
                              void* d_out, int out_size)
{
    const float* x   = (const float*)d_in[0];
    const float* Wh0 = (const float*)d_in[1];
    const float* bh0 = (const float*)d_in[2];
    const float* Wz0 = (const float*)d_in[3];
    const float* bz0 = (const float*)d_in[4];
    const float* Uh0 = (const float*)d_in[5];
    const float* Uz0 = (const float*)d_in[6];
    const float* Wh1 = (const float*)d_in[7];
    const float* bh1 = (const float*)d_in[8];
    const float* Wz1 = (const float*)d_in[9];
    const float* bz1 = (const float*)d_in[10];
    const float* Uh1 = (const float*)d_in[11];
    const float* Uz1 = (const float*)d_in[12];
    float* out = (float*)d_out;

    float *p_wh, *p_wz, *p_h1, *p_hT2, *p_zhT2;
    unsigned int* p_bar;
    cudaGetSymbolAddress((void**)&p_wh, g_wh);
    cudaGetSymbolAddress((void**)&p_wz, g_wz);
    cudaGetSymbolAddress((void**)&p_h1, g_h1);
    cudaGetSymbolAddress((void**)&p_hT2, g_hT2);
    cudaGetSymbolAddress((void**)&p_zhT2, g_zhT2);
    cudaGetSymbolAddress((void**)&p_bar, g_bar);

    cudaFuncSetAttribute(scan2_kernel,
                         cudaFuncAttributeMaxDynamicSharedMemorySize, SCAN2_SMEM_BYTES);

    dim3 pgrid(8, 2000);

    // ---- Layer 0 ----
    proj_kernel<<<pgrid, 256>>>(x, Wh0, Wz0, bh0, bz0, p_wh, p_wz);
    cudaMemsetAsync(p_hT2, 0, 16*512*4*sizeof(float));
    cudaMemsetAsync(p_bar, 0, 16*sizeof(unsigned int));
    scan2_kernel<<<128, 256, SCAN2_SMEM_BYTES>>>(p_wh, p_wz, Uh0, Uz0,
                                                 p_h1, p_hT2, p_zhT2, p_bar);

    // ---- Layer 1 ----
    proj_kernel<<<pgrid, 256>>>(p_h1, Wh1, Wz1, bh1, bz1, p_wh, p_wz);
    cudaMemsetAsync(p_hT2, 0, 16*512*4*sizeof(float));
    cudaMemsetAsync(p_bar, 0, 16*sizeof(unsigned int));
    scan2_kernel<<<128, 256, SCAN2_SMEM_BYTES>>>(p_wh, p_wz, Uh1, Uz1,
                                                 out, p_hT2, p_zhT2, p_bar);
}